// round 6
// baseline (speedup 1.0000x reference)
#include <cuda_runtime.h>
#include <cstdint>

// Shapes
//   x:      [32, 64, 64, 384] fp32   (50,331,648 elems)
//   w_qkv:  [384, 1152] fp32
//   w_out:  [384, 384]  fp32
//   b_out:  [384]       fp32
//   out:    [32, 64, 64, 384] fp32
// 2048 windows (b, nh, nw), 64 tokens each (i*8+j), 12 heads x 32.

#define SCALE_ATT 0.17677669529663687f   // 32^-0.5

// Attention output scratch: [2048*64 token-rows, 384] fp32 (201 MB, static device mem)
__device__ float g_O[50331648];

__device__ __forceinline__ float tf32r(float v) {
    uint32_t u;
    asm("cvt.rna.tf32.f32 %0, %1;" : "=r"(u) : "f"(v));
    return __uint_as_float(u);
}

__device__ __forceinline__ void mma_tf32(float (&d)[4], const uint32_t (&a)[4],
                                         const uint32_t (&b)[2]) {
    asm volatile(
        "mma.sync.aligned.m16n8k8.row.col.f32.tf32.tf32.f32 "
        "{%0,%1,%2,%3}, {%4,%5,%6,%7}, {%8,%9}, {%0,%1,%2,%3};\n"
        : "+f"(d[0]), "+f"(d[1]), "+f"(d[2]), "+f"(d[3])
        : "r"(a[0]), "r"(a[1]), "r"(a[2]), "r"(a[3]), "r"(b[0]), "r"(b[1]));
}

// ---------------------------------------------------------------------------
// K1: fused QKV GEMM + windowed attention. 1 CTA per window.
// smem (floats): xs[64][388] @0 ; ws[32][200] @24832 ;
//                qs[2][64][36] @31232 ; ks @35840 ; vs @40448 ; total 45056 fl
// ---------------------------------------------------------------------------
#define XS_STR 388
#define WS_STR 200
#define HB_STR 36
#define SMEM_K1_BYTES (45056 * 4)

__global__ void __launch_bounds__(256, 1) qkv_attn_kernel(
    const float* __restrict__ x, const float* __restrict__ wqkv)
{
    extern __shared__ float sm[];
    float* xs  = sm;
    float* ws  = sm + 24832;
    float* qs  = sm + 31232;
    float* ksm = sm + 35840;
    float* vsm = sm + 40448;

    const int tid  = threadIdx.x;
    const int warp = tid >> 5, lane = tid & 31;
    const int l4 = lane >> 2, lm = lane & 3;

    const int win = blockIdx.x;
    const int bb  = win >> 6, rem = win & 63, nhi = rem >> 3, nwi = rem & 7;

    // ---- load x window into smem (tf32-rounded), fully coalesced ----
    {
        const size_t base = ((size_t)(bb * 64 + nhi * 8) * 64 + nwi * 8) * 384;
        #pragma unroll
        for (int q = 0; q < 24; q++) {
            int f   = q * 256 + tid;          // 0..6143
            int row = f / 96;                 // token 0..63
            int c4  = (f - row * 96) * 4;     // col 0..380
            int i = row >> 3, j = row & 7;
            float4 v = *(const float4*)(x + base + ((size_t)i * 64 + j) * 384 + c4);
            float* d = xs + row * XS_STR + c4;
            d[0] = tf32r(v.x); d[1] = tf32r(v.y); d[2] = tf32r(v.z); d[3] = tf32r(v.w);
        }
    }
    __syncthreads();

    // ---- process heads in pairs: GEMM (64 x 192, K=384) then attention ----
    for (int hp = 0; hp < 6; hp++) {
        float acc[4][3][4];
        #pragma unroll
        for (int mi = 0; mi < 4; mi++)
            #pragma unroll
            for (int ni = 0; ni < 3; ni++)
                #pragma unroll
                for (int r = 0; r < 4; r++) acc[mi][ni][r] = 0.0f;

        // logical cols c (0..191): sec = c/64 (q/k/v), gcol = sec*384 + hp*64 + c%64
        float4 pf[6];
        #pragma unroll
        for (int q = 0; q < 6; q++) {            // prefetch k-tile 0
            int f = q * 256 + tid;               // 0..1535
            int row = f / 48;
            int seg = f - row * 48;
            int c4 = seg * 4;
            int sec = c4 >> 6, cin = c4 & 63;
            pf[q] = *(const float4*)(wqkv + (size_t)row * 1152 + sec * 384 + hp * 64 + cin);
        }

        for (int kt = 0; kt < 12; kt++) {
            __syncthreads();
            #pragma unroll
            for (int q = 0; q < 6; q++) {        // regs -> smem (tf32)
                int f = q * 256 + tid;
                int row = f / 48;
                int seg = f - row * 48;
                float* d = ws + row * WS_STR + seg * 4;
                d[0] = tf32r(pf[q].x); d[1] = tf32r(pf[q].y);
                d[2] = tf32r(pf[q].z); d[3] = tf32r(pf[q].w);
            }
            __syncthreads();
            if (kt < 11) {                       // prefetch next k-tile
                #pragma unroll
                for (int q = 0; q < 6; q++) {
                    int f = q * 256 + tid;
                    int row = f / 48;
                    int seg = f - row * 48;
                    int c4 = seg * 4;
                    int sec = c4 >> 6, cin = c4 & 63;
                    pf[q] = *(const float4*)(wqkv + (size_t)((kt + 1) * 32 + row) * 1152
                                             + sec * 384 + hp * 64 + cin);
                }
            }
            #pragma unroll
            for (int ks = 0; ks < 4; ks++) {     // 4 x k8 steps
                uint32_t bf[3][2];
                #pragma unroll
                for (int ni = 0; ni < 3; ni++) {
                    int n = (3 * warp + ni) * 8 + l4;
                    bf[ni][0] = *(const uint32_t*)(ws + (ks * 8 + lm) * WS_STR + n);
                    bf[ni][1] = *(const uint32_t*)(ws + (ks * 8 + lm + 4) * WS_STR + n);
                }
                #pragma unroll
                for (int mi = 0; mi < 4; mi++) {
                    uint32_t af[4];
                    int r0 = mi * 16 + l4;
                    int ka = kt * 32 + ks * 8 + lm;
                    af[0] = *(const uint32_t*)(xs + r0 * XS_STR + ka);
                    af[1] = *(const uint32_t*)(xs + (r0 + 8) * XS_STR + ka);
                    af[2] = *(const uint32_t*)(xs + r0 * XS_STR + ka + 4);
                    af[3] = *(const uint32_t*)(xs + (r0 + 8) * XS_STR + ka + 4);
                    #pragma unroll
                    for (int ni = 0; ni < 3; ni++) mma_tf32(acc[mi][ni], af, bf[ni]);
                }
            }
        }

        // ---- scatter acc into q/k/v head buffers ----
        #pragma unroll
        for (int mi = 0; mi < 4; mi++)
            #pragma unroll
            for (int ni = 0; ni < 3; ni++) {
                int nlog = (3 * warp + ni) * 8 + 2 * lm;
                #pragma unroll
                for (int r = 0; r < 4; r++) {
                    int row = mi * 16 + l4 + ((r & 2) ? 8 : 0);
                    int col = nlog + (r & 1);
                    int sec = col >> 6;
                    int wth = col & 63;
                    float* buf = (sec == 0) ? qs : ((sec == 1) ? ksm : vsm);
                    buf[((wth >> 5) * 64 + row) * HB_STR + (wth & 31)] = acc[mi][ni][r];
                }
            }
        __syncthreads();

        // ---- attention (fp32): warps 0-3 -> head hp*2, 4-7 -> hp*2+1 ----
        {
            const int hip = warp >> 2;
            const int wg  = warp & 3;
            const int row = wg * 16 + (lane >> 1);   // token row of S / O
            const int jb  = (lane & 1) * 32;         // column half
            const float* qp = qs + (hip * 64 + row) * HB_STR;
            float4 qv[8];
            #pragma unroll
            for (int c = 0; c < 8; c++) qv[c] = *(const float4*)(qp + c * 4);

            float sreg[32];
            #pragma unroll
            for (int jj = 0; jj < 32; jj++) {
                const float* kp = ksm + (hip * 64 + jb + jj) * HB_STR;
                float d = 0.0f;
                #pragma unroll
                for (int c = 0; c < 8; c++) {
                    float4 kk = *(const float4*)(kp + c * 4);
                    d += qv[c].x * kk.x + qv[c].y * kk.y + qv[c].z * kk.z + qv[c].w * kk.w;
                }
                sreg[jj] = d * SCALE_ATT;
            }
            float mx = sreg[0];
            #pragma unroll
            for (int jj = 1; jj < 32; jj++) mx = fmaxf(mx, sreg[jj]);
            mx = fmaxf(mx, __shfl_xor_sync(0xffffffffu, mx, 1));
            float ssum = 0.0f;
            #pragma unroll
            for (int jj = 0; jj < 32; jj++) { sreg[jj] = __expf(sreg[jj] - mx); ssum += sreg[jj]; }
            ssum += __shfl_xor_sync(0xffffffffu, ssum, 1);
            const float inv = 1.0f / ssum;

            float o[32];
            #pragma unroll
            for (int c = 0; c < 32; c++) o[c] = 0.0f;
            #pragma unroll
            for (int jj = 0; jj < 32; jj++) {
                float p = sreg[jj] * inv;
                const float* vp = vsm + (hip * 64 + jb + jj) * HB_STR;
                #pragma unroll
                for (int c = 0; c < 8; c++) {
                    float4 vv = *(const float4*)(vp + c * 4);
                    o[c * 4 + 0] += p * vv.x; o[c * 4 + 1] += p * vv.y;
                    o[c * 4 + 2] += p * vv.z; o[c * 4 + 3] += p * vv.w;
                }
            }
            #pragma unroll
            for (int c = 0; c < 32; c++) o[c] += __shfl_xor_sync(0xffffffffu, o[c], 1);

            float* dst = g_O + ((size_t)win * 64 + row) * 384 + (hp * 2 + hip) * 32;
            if ((lane & 1) == 0) {
                *(float4*)(dst + 0)  = make_float4(o[0],  o[1],  o[2],  o[3]);
                *(float4*)(dst + 4)  = make_float4(o[4],  o[5],  o[6],  o[7]);
                *(float4*)(dst + 8)  = make_float4(o[8],  o[9],  o[10], o[11]);
                *(float4*)(dst + 12) = make_float4(o[12], o[13], o[14], o[15]);
            } else {
                *(float4*)(dst + 16) = make_float4(o[16], o[17], o[18], o[19]);
                *(float4*)(dst + 20) = make_float4(o[20], o[21], o[22], o[23]);
                *(float4*)(dst + 24) = make_float4(o[24], o[25], o[26], o[27]);
                *(float4*)(dst + 28) = make_float4(o[28], o[29], o[30], o[31]);
            }
        }
    }
}

// ---------------------------------------------------------------------------
// K2: out = O @ w_out + b_out, with un-windowing scatter.
// CTA tile 128x128, K tiled by 32. Grid (1024, 3).
// ---------------------------------------------------------------------------
__global__ void __launch_bounds__(256) out_proj_kernel(
    const float* __restrict__ wout, const float* __restrict__ bout,
    float* __restrict__ out)
{
    __shared__ float osA[128 * 36];   // A tile [128 rows][32 k] (+pad)
    __shared__ float wsB[32 * 136];   // B tile [32 k][128 n] (+pad)

    const int tid  = threadIdx.x;
    const int warp = tid >> 5, lane = tid & 31;
    const int l4 = lane >> 2, lm = lane & 3;
    const int mg = warp & 1, ng = warp >> 1;   // warp: 64-row group x 32-col group

    const int mb = blockIdx.x;                 // 0..1023
    const int nb = blockIdx.y;                 // 0..2
    const size_t row0 = (size_t)mb * 128;

    float acc[4][4][4];
    #pragma unroll
    for (int mi = 0; mi < 4; mi++)
        #pragma unroll
        for (int ni = 0; ni < 4; ni++)
            #pragma unroll
            for (int r = 0; r < 4; r++) acc[mi][ni][r] = 0.0f;

    float4 pa[4], pb[4];
    #pragma unroll
    for (int q = 0; q < 4; q++) {              // prefetch k-tile 0
        int f = q * 256 + tid;                 // 0..1023
        int rA = f >> 3, cA = (f & 7) * 4;
        pa[q] = *(const float4*)(g_O + (row0 + rA) * 384 + cA);
        int rB = f >> 5, cB = (f & 31) * 4;
        pb[q] = *(const float4*)(wout + (size_t)rB * 384 + nb * 128 + cB);
    }

    for (int kt = 0; kt < 12; kt++) {
        __syncthreads();
        #pragma unroll
        for (int q = 0; q < 4; q++) {
            int f = q * 256 + tid;
            int rA = f >> 3, cA = (f & 7) * 4;
            float* dA = osA + rA * 36 + cA;
            dA[0]=tf32r(pa[q].x); dA[1]=tf32r(pa[q].y); dA[2]=tf32r(pa[q].z); dA[3]=tf32r(pa[q].w);
            int rB = f >> 5, cB = (f & 31) * 4;
            float* dB = wsB + rB * 136 + cB;
            dB[0]=tf32r(pb[q].x); dB[1]=tf32r(pb[q].y); dB[2]=tf32r(pb[q].z); dB[3]=tf32r(pb[q].w);
        }
        __syncthreads();
        if (kt < 11) {
            #pragma unroll
            for (int q = 0; q < 4; q++) {
                int f = q * 256 + tid;
                int rA = f >> 3, cA = (f & 7) * 4;
                pa[q] = *(const float4*)(g_O + (row0 + rA) * 384 + (kt + 1) * 32 + cA);
                int rB = f >> 5, cB = (f & 31) * 4;
                pb[q] = *(const float4*)(wout + (size_t)((kt + 1) * 32 + rB) * 384
                                         + nb * 128 + cB);
            }
        }
        #pragma unroll
        for (int ks = 0; ks < 4; ks++) {
            uint32_t bf[4][2];
            #pragma unroll
            for (int ni = 0; ni < 4; ni++) {
                int n = ng * 32 + ni * 8 + l4;
                bf[ni][0] = *(const uint32_t*)(wsB + (ks * 8 + lm) * 136 + n);
                bf[ni][1] = *(const uint32_t*)(wsB + (ks * 8 + lm + 4) * 136 + n);
            }
            #pragma unroll
            for (int mi = 0; mi < 4; mi++) {
                uint32_t af[4];
                int r0 = mg * 64 + mi * 16 + l4;
                int kl = ks * 8 + lm;
                af[0] = *(const uint32_t*)(osA + r0 * 36 + kl);
                af[1] = *(const uint32_t*)(osA + (r0 + 8) * 36 + kl);
                af[2] = *(const uint32_t*)(osA + r0 * 36 + kl + 4);
                af[3] = *(const uint32_t*)(osA + (r0 + 8) * 36 + kl + 4);
                #pragma unroll
                for (int ni = 0; ni < 4; ni++) mma_tf32(acc[mi][ni], af, bf[ni]);
            }
        }
    }

    // epilogue: bias + un-window scatter
    #pragma unroll
    for (int ni = 0; ni < 4; ni++) {
        int col = nb * 128 + ng * 32 + ni * 8 + 2 * lm;
        float bv0 = __ldg(bout + col), bv1 = __ldg(bout + col + 1);
        #pragma unroll
        for (int mi = 0; mi < 4; mi++) {
            #pragma unroll
            for (int half = 0; half < 2; half++) {
                int grow = (int)row0 + mg * 64 + mi * 16 + l4 + half * 8;
                int wwin = grow >> 6, t = grow & 63;
                int bbb = wwin >> 6, rr = wwin & 63;
                int nhi = rr >> 3, nwi = rr & 7;
                int i = t >> 3, j = t & 7;
                size_t g = (((size_t)(bbb * 64 + nhi * 8 + i)) * 64 + nwi * 8 + j) * 384 + col;
                float2 v;
                v.x = acc[mi][ni][half * 2 + 0] + bv0;
                v.y = acc[mi][ni][half * 2 + 1] + bv1;
                *(float2*)(out + g) = v;
            }
        }
    }
}

extern "C" void kernel_launch(void* const* d_in, const int* in_sizes, int n_in,
                              void* d_out, int out_size) {
    (void)in_sizes; (void)n_in; (void)out_size;
    const float* x    = (const float*)d_in[0];
    const float* wqkv = (const float*)d_in[1];
    const float* wout = (const float*)d_in[2];
    const float* bout = (const float*)d_in[3];
    float* out = (float*)d_out;

    cudaFuncSetAttribute(qkv_attn_kernel,
                         cudaFuncAttributeMaxDynamicSharedMemorySize, SMEM_K1_BYTES);
    qkv_attn_kernel<<<2048, 256, SMEM_K1_BYTES>>>(x, wqkv);
    out_proj_kernel<<<dim3(1024, 3), 256>>>(wout, bout, out);
}

// round 7
// speedup vs baseline: 1.4161x; 1.4161x over previous
#include <cuda_runtime.h>
#include <cstdint>

// Shapes
//   x:      [32, 64, 64, 384] fp32
//   w_qkv:  [384, 1152] fp32
//   w_out:  [384, 384]  fp32
//   b_out:  [384]       fp32
//   out:    [32, 64, 64, 384] fp32
// 2048 windows, 64 tokens each, 12 heads x 32.

#define SCALE_ATT 0.17677669529663687f   // 32^-0.5

// Attention output scratch: [2048*64, 384] fp32
__device__ float g_O[50331648];

__device__ __forceinline__ float tf32r(float v) {
    uint32_t u;
    asm("cvt.rna.tf32.f32 %0, %1;" : "=r"(u) : "f"(v));
    return __uint_as_float(u);
}

__device__ __forceinline__ void mma_tf32(float (&d)[4], const uint32_t (&a)[4],
                                         const uint32_t (&b)[2]) {
    asm volatile(
        "mma.sync.aligned.m16n8k8.row.col.f32.tf32.tf32.f32 "
        "{%0,%1,%2,%3}, {%4,%5,%6,%7}, {%8,%9}, {%0,%1,%2,%3};\n"
        : "+f"(d[0]), "+f"(d[1]), "+f"(d[2]), "+f"(d[3])
        : "r"(a[0]), "r"(a[1]), "r"(a[2]), "r"(a[3]), "r"(b[0]), "r"(b[1]));
}

// ---------------------------------------------------------------------------
// K1: fused QKV GEMM + windowed attention (tensor-core attention).
// smem (floats): xs[64][388] @0 ; ws[32][200] @24832 ;
//                qs @31232 ; ks @35840 ; vs @40448 ; total 45056 fl (180KB)
// P buffers reuse qs/ks region (8 warps x 16 x 68 = 8704 fl <= 9216 fl).
// ---------------------------------------------------------------------------
#define XS_STR 388
#define WS_STR 200
#define HB_STR 36
#define P_STR  68
#define SMEM_K1_BYTES (45056 * 4)

__global__ void __launch_bounds__(256, 1) qkv_attn_kernel(
    const float* __restrict__ x, const float* __restrict__ wqkv)
{
    extern __shared__ float sm[];
    float* xs  = sm;
    float* ws  = sm + 24832;
    float* qs  = sm + 31232;
    float* ksm = sm + 35840;
    float* vsm = sm + 40448;

    const int tid  = threadIdx.x;
    const int warp = tid >> 5, lane = tid & 31;
    const int l4 = lane >> 2, lm = lane & 3;

    const int win = blockIdx.x;
    const int bb  = win >> 6, rem = win & 63, nhi = rem >> 3, nwi = rem & 7;

    // ---- load x window into smem (tf32-rounded), coalesced ----
    {
        const size_t base = ((size_t)(bb * 64 + nhi * 8) * 64 + nwi * 8) * 384;
        #pragma unroll
        for (int q = 0; q < 24; q++) {
            int f   = q * 256 + tid;
            int row = f / 96;
            int c4  = (f - row * 96) * 4;
            int i = row >> 3, j = row & 7;
            float4 v = *(const float4*)(x + base + ((size_t)i * 64 + j) * 384 + c4);
            float* d = xs + row * XS_STR + c4;
            d[0] = tf32r(v.x); d[1] = tf32r(v.y); d[2] = tf32r(v.z); d[3] = tf32r(v.w);
        }
    }
    __syncthreads();

    // ---- head pairs: GEMM (64 x 192, K=384) then tensor-core attention ----
    for (int hp = 0; hp < 6; hp++) {
        float acc[4][3][4];
        #pragma unroll
        for (int mi = 0; mi < 4; mi++)
            #pragma unroll
            for (int ni = 0; ni < 3; ni++)
                #pragma unroll
                for (int r = 0; r < 4; r++) acc[mi][ni][r] = 0.0f;

        float4 pf[6];
        #pragma unroll
        for (int q = 0; q < 6; q++) {            // prefetch k-tile 0
            int f = q * 256 + tid;
            int row = f / 48;
            int seg = f - row * 48;
            int c4 = seg * 4;
            int sec = c4 >> 6, cin = c4 & 63;
            pf[q] = *(const float4*)(wqkv + (size_t)row * 1152 + sec * 384 + hp * 64 + cin);
        }

        for (int kt = 0; kt < 12; kt++) {
            __syncthreads();
            #pragma unroll
            for (int q = 0; q < 6; q++) {
                int f = q * 256 + tid;
                int row = f / 48;
                int seg = f - row * 48;
                float* d = ws + row * WS_STR + seg * 4;
                d[0] = tf32r(pf[q].x); d[1] = tf32r(pf[q].y);
                d[2] = tf32r(pf[q].z); d[3] = tf32r(pf[q].w);
            }
            __syncthreads();
            if (kt < 11) {
                #pragma unroll
                for (int q = 0; q < 6; q++) {
                    int f = q * 256 + tid;
                    int row = f / 48;
                    int seg = f - row * 48;
                    int c4 = seg * 4;
                    int sec = c4 >> 6, cin = c4 & 63;
                    pf[q] = *(const float4*)(wqkv + (size_t)((kt + 1) * 32 + row) * 1152
                                             + sec * 384 + hp * 64 + cin);
                }
            }
            #pragma unroll
            for (int ks = 0; ks < 4; ks++) {
                uint32_t bf[3][2];
                #pragma unroll
                for (int ni = 0; ni < 3; ni++) {
                    int n = (3 * warp + ni) * 8 + l4;
                    bf[ni][0] = *(const uint32_t*)(ws + (ks * 8 + lm) * WS_STR + n);
                    bf[ni][1] = *(const uint32_t*)(ws + (ks * 8 + lm + 4) * WS_STR + n);
                }
                #pragma unroll
                for (int mi = 0; mi < 4; mi++) {
                    uint32_t af[4];
                    int r0 = mi * 16 + l4;
                    int ka = kt * 32 + ks * 8 + lm;
                    af[0] = *(const uint32_t*)(xs + r0 * XS_STR + ka);
                    af[1] = *(const uint32_t*)(xs + (r0 + 8) * XS_STR + ka);
                    af[2] = *(const uint32_t*)(xs + r0 * XS_STR + ka + 4);
                    af[3] = *(const uint32_t*)(xs + (r0 + 8) * XS_STR + ka + 4);
                    #pragma unroll
                    for (int ni = 0; ni < 3; ni++) mma_tf32(acc[mi][ni], af, bf[ni]);
                }
            }
        }

        // ---- scatter acc into q/k/v head buffers (tf32; q pre-scaled) ----
        #pragma unroll
        for (int mi = 0; mi < 4; mi++)
            #pragma unroll
            for (int ni = 0; ni < 3; ni++) {
                int nlog = (3 * warp + ni) * 8 + 2 * lm;
                #pragma unroll
                for (int r = 0; r < 4; r++) {
                    int row = mi * 16 + l4 + ((r & 2) ? 8 : 0);
                    int col = nlog + (r & 1);
                    int sec = col >> 6;
                    int wth = col & 63;
                    float v = acc[mi][ni][r];
                    if (sec == 0) v *= SCALE_ATT;
                    float* buf = (sec == 0) ? qs : ((sec == 1) ? ksm : vsm);
                    buf[((wth >> 5) * 64 + row) * HB_STR + (wth & 31)] = tf32r(v);
                }
            }
        __syncthreads();

        // ---- tensor-core attention ----
        {
            const int hip = warp >> 2;          // head within pair
            const int wg  = warp & 3;           // 16-row m-tile
            const float* qbase = qs  + hip * 64 * HB_STR;
            const float* kbase = ksm + hip * 64 * HB_STR;
            const float* vbase = vsm + hip * 64 * HB_STR;
            float* pw = qs + warp * (16 * P_STR);   // per-warp P buffer

            // S = (Q*scale) . K^T   [16 x 64], K=32
            float s[8][4];
            #pragma unroll
            for (int nt = 0; nt < 8; nt++)
                #pragma unroll
                for (int r = 0; r < 4; r++) s[nt][r] = 0.0f;

            #pragma unroll
            for (int ks = 0; ks < 4; ks++) {
                int kk = ks * 8 + lm;
                uint32_t af[4];
                int r0 = wg * 16 + l4;
                af[0] = *(const uint32_t*)(qbase + r0 * HB_STR + kk);
                af[1] = *(const uint32_t*)(qbase + (r0 + 8) * HB_STR + kk);
                af[2] = *(const uint32_t*)(qbase + r0 * HB_STR + kk + 4);
                af[3] = *(const uint32_t*)(qbase + (r0 + 8) * HB_STR + kk + 4);
                #pragma unroll
                for (int nt = 0; nt < 8; nt++) {
                    uint32_t bf[2];
                    bf[0] = *(const uint32_t*)(kbase + (nt * 8 + l4) * HB_STR + kk);
                    bf[1] = *(const uint32_t*)(kbase + (nt * 8 + l4) * HB_STR + kk + 4);
                    mma_tf32(s[nt], af, bf);
                }
            }

            // row softmax (rows l4 and l4+8 of this warp's 16-row tile);
            // each row lives in the 4 lanes of a quad -> shfl_xor 1,2.
            float mx0 = s[0][0], mx1 = s[0][2];
            #pragma unroll
            for (int nt = 0; nt < 8; nt++) {
                mx0 = fmaxf(mx0, fmaxf(s[nt][0], s[nt][1]));
                mx1 = fmaxf(mx1, fmaxf(s[nt][2], s[nt][3]));
            }
            mx0 = fmaxf(mx0, __shfl_xor_sync(0xffffffffu, mx0, 1));
            mx0 = fmaxf(mx0, __shfl_xor_sync(0xffffffffu, mx0, 2));
            mx1 = fmaxf(mx1, __shfl_xor_sync(0xffffffffu, mx1, 1));
            mx1 = fmaxf(mx1, __shfl_xor_sync(0xffffffffu, mx1, 2));

            float sum0 = 0.0f, sum1 = 0.0f;
            #pragma unroll
            for (int nt = 0; nt < 8; nt++) {
                s[nt][0] = __expf(s[nt][0] - mx0); sum0 += s[nt][0];
                s[nt][1] = __expf(s[nt][1] - mx0); sum0 += s[nt][1];
                s[nt][2] = __expf(s[nt][2] - mx1); sum1 += s[nt][2];
                s[nt][3] = __expf(s[nt][3] - mx1); sum1 += s[nt][3];
            }
            sum0 += __shfl_xor_sync(0xffffffffu, sum0, 1);
            sum0 += __shfl_xor_sync(0xffffffffu, sum0, 2);
            sum1 += __shfl_xor_sync(0xffffffffu, sum1, 1);
            sum1 += __shfl_xor_sync(0xffffffffu, sum1, 2);
            const float inv0 = 1.0f / sum0;
            const float inv1 = 1.0f / sum1;

            // all warps must finish reading qs/ksm before P clobbers them
            __syncthreads();

            #pragma unroll
            for (int nt = 0; nt < 8; nt++) {
                float2 v0 = make_float2(tf32r(s[nt][0]), tf32r(s[nt][1]));
                float2 v1 = make_float2(tf32r(s[nt][2]), tf32r(s[nt][3]));
                *(float2*)(pw + l4 * P_STR + nt * 8 + 2 * lm) = v0;
                *(float2*)(pw + (l4 + 8) * P_STR + nt * 8 + 2 * lm) = v1;
            }
            __syncwarp();

            // O = P . V   [16 x 32], K=64  (unnormalized; scale rows at the end)
            float o[4][4];
            #pragma unroll
            for (int nt = 0; nt < 4; nt++)
                #pragma unroll
                for (int r = 0; r < 4; r++) o[nt][r] = 0.0f;

            #pragma unroll
            for (int ks = 0; ks < 8; ks++) {
                int kk = ks * 8 + lm;
                uint32_t af[4];
                af[0] = *(const uint32_t*)(pw + l4 * P_STR + kk);
                af[1] = *(const uint32_t*)(pw + (l4 + 8) * P_STR + kk);
                af[2] = *(const uint32_t*)(pw + l4 * P_STR + kk + 4);
                af[3] = *(const uint32_t*)(pw + (l4 + 8) * P_STR + kk + 4);
                #pragma unroll
                for (int nt = 0; nt < 4; nt++) {
                    uint32_t bf[2];
                    bf[0] = *(const uint32_t*)(vbase + kk * HB_STR + nt * 8 + l4);
                    bf[1] = *(const uint32_t*)(vbase + (kk + 4) * HB_STR + nt * 8 + l4);
                    mma_tf32(o[nt], af, bf);
                }
            }

            float* dst = g_O + ((size_t)win * 64 + wg * 16 + l4) * 384
                       + (hp * 2 + hip) * 32;
            #pragma unroll
            for (int nt = 0; nt < 4; nt++) {
                float2 v0 = make_float2(o[nt][0] * inv0, o[nt][1] * inv0);
                float2 v1 = make_float2(o[nt][2] * inv1, o[nt][3] * inv1);
                *(float2*)(dst + nt * 8 + 2 * lm) = v0;
                *(float2*)(dst + 8 * 384 + nt * 8 + 2 * lm) = v1;
            }
        }
    }
}

// ---------------------------------------------------------------------------
// K2: out = O @ w_out + b_out, with un-windowing scatter.
// CTA tile 128x128, K tiled by 32. Grid (3, 1024): nb fastest so the 3 CTAs
// sharing an A row-block run together -> g_O read once from DRAM via L2.
// ---------------------------------------------------------------------------
__global__ void __launch_bounds__(256) out_proj_kernel(
    const float* __restrict__ wout, const float* __restrict__ bout,
    float* __restrict__ out)
{
    __shared__ float osA[128 * 36];
    __shared__ float wsB[32 * 136];

    const int tid  = threadIdx.x;
    const int warp = tid >> 5, lane = tid & 31;
    const int l4 = lane >> 2, lm = lane & 3;
    const int mg = warp & 1, ng = warp >> 1;

    const int nb = blockIdx.x;                 // 0..2
    const int mb = blockIdx.y;                 // 0..1023
    const size_t row0 = (size_t)mb * 128;

    float acc[4][4][4];
    #pragma unroll
    for (int mi = 0; mi < 4; mi++)
        #pragma unroll
        for (int ni = 0; ni < 4; ni++)
            #pragma unroll
            for (int r = 0; r < 4; r++) acc[mi][ni][r] = 0.0f;

    float4 pa[4], pb[4];
    #pragma unroll
    for (int q = 0; q < 4; q++) {
        int f = q * 256 + tid;
        int rA = f >> 3, cA = (f & 7) * 4;
        pa[q] = *(const float4*)(g_O + (row0 + rA) * 384 + cA);
        int rB = f >> 5, cB = (f & 31) * 4;
        pb[q] = *(const float4*)(wout + (size_t)rB * 384 + nb * 128 + cB);
    }

    for (int kt = 0; kt < 12; kt++) {
        __syncthreads();
        #pragma unroll
        for (int q = 0; q < 4; q++) {
            int f = q * 256 + tid;
            int rA = f >> 3, cA = (f & 7) * 4;
            float* dA = osA + rA * 36 + cA;
            dA[0]=tf32r(pa[q].x); dA[1]=tf32r(pa[q].y); dA[2]=tf32r(pa[q].z); dA[3]=tf32r(pa[q].w);
            int rB = f >> 5, cB = (f & 31) * 4;
            float* dB = wsB + rB * 136 + cB;
            dB[0]=tf32r(pb[q].x); dB[1]=tf32r(pb[q].y); dB[2]=tf32r(pb[q].z); dB[3]=tf32r(pb[q].w);
        }
        __syncthreads();
        if (kt < 11) {
            #pragma unroll
            for (int q = 0; q < 4; q++) {
                int f = q * 256 + tid;
                int rA = f >> 3, cA = (f & 7) * 4;
                pa[q] = *(const float4*)(g_O + (row0 + rA) * 384 + (kt + 1) * 32 + cA);
                int rB = f >> 5, cB = (f & 31) * 4;
                pb[q] = *(const float4*)(wout + (size_t)((kt + 1) * 32 + rB) * 384
                                         + nb * 128 + cB);
            }
        }
        #pragma unroll
        for (int ks = 0; ks < 4; ks++) {
            uint32_t bf[4][2];
            #pragma unroll
            for (int ni = 0; ni < 4; ni++) {
                int n = ng * 32 + ni * 8 + l4;
                bf[ni][0] = *(const uint32_t*)(wsB + (ks * 8 + lm) * 136 + n);
                bf[ni][1] = *(const uint32_t*)(wsB + (ks * 8 + lm + 4) * 136 + n);
            }
            #pragma unroll
            for (int mi = 0; mi < 4; mi++) {
                uint32_t af[4];
                int r0 = mg * 64 + mi * 16 + l4;
                int kl = ks * 8 + lm;
                af[0] = *(const uint32_t*)(osA + r0 * 36 + kl);
                af[1] = *(const uint32_t*)(osA + (r0 + 8) * 36 + kl);
                af[2] = *(const uint32_t*)(osA + r0 * 36 + kl + 4);
                af[3] = *(const uint32_t*)(osA + (r0 + 8) * 36 + kl + 4);
                #pragma unroll
                for (int ni = 0; ni < 4; ni++) mma_tf32(acc[mi][ni], af, bf[ni]);
            }
        }
    }

    #pragma unroll
    for (int ni = 0; ni < 4; ni++) {
        int col = nb * 128 + ng * 32 + ni * 8 + 2 * lm;
        float bv0 = __ldg(bout + col), bv1 = __ldg(bout + col + 1);
        #pragma unroll
        for (int mi = 0; mi < 4; mi++) {
            #pragma unroll
            for (int half = 0; half < 2; half++) {
                int grow = (int)row0 + mg * 64 + mi * 16 + l4 + half * 8;
                int wwin = grow >> 6, t = grow & 63;
                int bbb = wwin >> 6, rr = wwin & 63;
                int nhi = rr >> 3, nwi = rr & 7;
                int i = t >> 3, j = t & 7;
                size_t g = (((size_t)(bbb * 64 + nhi * 8 + i)) * 64 + nwi * 8 + j) * 384 + col;
                float2 v;
                v.x = acc[mi][ni][half * 2 + 0] + bv0;
                v.y = acc[mi][ni][half * 2 + 1] + bv1;
                *(float2*)(out + g) = v;
            }
        }
    }
}

extern "C" void kernel_launch(void* const* d_in, const int* in_sizes, int n_in,
                              void* d_out, int out_size) {
    (void)in_sizes; (void)n_in; (void)out_size;
    const float* x    = (const float*)d_in[0];
    const float* wqkv = (const float*)d_in[1];
    const float* wout = (const float*)d_in[2];
    const float* bout = (const float*)d_in[3];
    float* out = (float*)d_out;

    cudaFuncSetAttribute(qkv_attn_kernel,
                         cudaFuncAttributeMaxDynamicSharedMemorySize, SMEM_K1_BYTES);
    qkv_attn_kernel<<<2048, 256, SMEM_K1_BYTES>>>(x, wqkv);
    out_proj_kernel<<<dim3(3, 1024), 256>>>(wout, bout, out);
}

// round 9
// speedup vs baseline: 2.4678x; 1.7426x over previous
#include <cuda_runtime.h>
#include <cuda_fp16.h>
#include <cstdint>

// Shapes
//   x:      [32, 64, 64, 384] fp32
//   w_qkv:  [384, 1152] fp32
//   w_out:  [384, 384]  fp32
//   b_out:  [384]       fp32
//   out:    [32, 64, 64, 384] fp32
// 2048 windows, 64 tokens each, 12 heads x 32.

#define SCALE_ATT 0.17677669529663687f   // 32^-0.5

// Scratch (static device mem, allowed)
__device__ float  g_O[50331648];        // attention out [2048*64][384] fp32
__device__ __half g_Wqh[1152 * 392];    // w_qkv^T  [n=1152][k=384 +8 pad] fp16
__device__ __half g_Woh[384 * 392];     // w_out^T  [n=384][k=384 +8 pad] fp16

__device__ __forceinline__ void mma_f16(float (&d)[4], const uint32_t (&a)[4],
                                        const uint32_t (&b)[2]) {
    asm volatile(
        "mma.sync.aligned.m16n8k16.row.col.f32.f16.f16.f32 "
        "{%0,%1,%2,%3}, {%4,%5,%6,%7}, {%8,%9}, {%0,%1,%2,%3};\n"
        : "+f"(d[0]), "+f"(d[1]), "+f"(d[2]), "+f"(d[3])
        : "r"(a[0]), "r"(a[1]), "r"(a[2]), "r"(a[3]), "r"(b[0]), "r"(b[1]));
}

// ---------------------------------------------------------------------------
// K0: transpose + fp16-convert weights.
// ---------------------------------------------------------------------------
__global__ void prep_weights(const float* __restrict__ wqkv,
                             const float* __restrict__ wout)
{
    int i = blockIdx.x * 256 + threadIdx.x;
    if (i < 384 * 1152) {
        int k = i / 1152, n = i % 1152;          // coalesced read along n
        g_Wqh[n * 392 + k] = __float2half_rn(wqkv[i]);
    } else {
        int j = i - 384 * 1152;
        if (j < 384 * 384) {
            int k = j / 384, n = j % 384;
            g_Woh[n * 392 + k] = __float2half_rn(wout[j]);
        }
    }
}

// ---------------------------------------------------------------------------
// K1: fused QKV GEMM + windowed attention, fp16 mma. 1 CTA per window, occ 2.
// smem halves: xs[64][392] @0 ; ws0[192][40] @25088 ; ws1 @32768 ;
//              qs[2][64][40] @40448 ; ks @45568 ; vs[2][32][72] @50688
// total 55296 halves = 110592 B. P overlays qs/ks (8*16*72 = 9216 <= 10240).
// ---------------------------------------------------------------------------
#define XH 392
#define WH 40
#define QH 40
#define VH 72
#define PH 72
#define SMEM_K1_BYTES (55296 * 2)

__global__ void __launch_bounds__(256, 2) qkv_attn_kernel(
    const float* __restrict__ x)
{
    extern __shared__ __half smh[];
    __half* xs  = smh;
    __half* ws0 = smh + 25088;
    __half* ws1 = smh + 32768;
    __half* qs  = smh + 40448;
    __half* ksb = smh + 45568;
    __half* vsb = smh + 50688;

    const int tid  = threadIdx.x;
    const int warp = tid >> 5, lane = tid & 31;
    const int l4 = lane >> 2, lm = lane & 3;

    const int win = blockIdx.x;
    const int bb  = win >> 6, rem = win & 63, nhi = rem >> 3, nwi = rem & 7;

    // ---- load x window -> fp16 smem, coalesced ----
    {
        const size_t base = ((size_t)(bb * 64 + nhi * 8) * 64 + nwi * 8) * 384;
        #pragma unroll
        for (int q = 0; q < 24; q++) {
            int f   = q * 256 + tid;
            int row = f / 96;
            int c4  = (f - row * 96) * 4;
            int i = row >> 3, j = row & 7;
            float4 v = *(const float4*)(x + base + ((size_t)i * 64 + j) * 384 + c4);
            __half2* d = (__half2*)(xs + row * XH + c4);
            d[0] = __floats2half2_rn(v.x, v.y);
            d[1] = __floats2half2_rn(v.z, v.w);
        }
    }
    __syncthreads();

    // ---- head pairs: QKV GEMM (64 x 192, K=384) then attention ----
    for (int hp = 0; hp < 6; hp++) {
        float acc[4][3][4];
        #pragma unroll
        for (int mi = 0; mi < 4; mi++)
            #pragma unroll
            for (int ni = 0; ni < 3; ni++)
                #pragma unroll
                for (int r = 0; r < 4; r++) acc[mi][ni][r] = 0.0f;

        // weight tile mapping: 192 rows (n) x 32 halves (k) per kt; 3 uint4/thread
        const __half* gwp[3];
        int so[3];
        #pragma unroll
        for (int q = 0; q < 3; q++) {
            int u = q * 256 + tid;
            int rown = u >> 2, seg = u & 3;
            int sec = rown >> 6, nin = rown & 63;
            gwp[q] = g_Wqh + (size_t)(sec * 384 + hp * 64 + nin) * 392 + seg * 8;
            so[q]  = rown * WH + seg * 8;
        }
        uint4 pf[3];
        #pragma unroll
        for (int q = 0; q < 3; q++) pf[q] = *(const uint4*)(gwp[q]);

        for (int kt = 0; kt < 12; kt++) {
            __half* wsp = (kt & 1) ? ws1 : ws0;
            #pragma unroll
            for (int q = 0; q < 3; q++) *(uint4*)(wsp + so[q]) = pf[q];
            __syncthreads();
            if (kt < 11) {
                #pragma unroll
                for (int q = 0; q < 3; q++)
                    pf[q] = *(const uint4*)(gwp[q] + (kt + 1) * 32);
            }
            #pragma unroll
            for (int ks = 0; ks < 2; ks++) {
                const int kk = ks * 16 + 2 * lm;
                uint32_t bf[3][2];
                #pragma unroll
                for (int ni = 0; ni < 3; ni++) {
                    const __half* p = wsp + ((3 * warp + ni) * 8 + l4) * WH + kk;
                    bf[ni][0] = *(const uint32_t*)p;
                    bf[ni][1] = *(const uint32_t*)(p + 8);
                }
                #pragma unroll
                for (int mi = 0; mi < 4; mi++) {
                    const __half* p = xs + (mi * 16 + l4) * XH + kt * 32 + kk;
                    uint32_t af[4];
                    af[0] = *(const uint32_t*)p;
                    af[1] = *(const uint32_t*)(p + 8 * XH);
                    af[2] = *(const uint32_t*)(p + 8);
                    af[3] = *(const uint32_t*)(p + 8 * XH + 8);
                    #pragma unroll
                    for (int ni = 0; ni < 3; ni++) mma_f16(acc[mi][ni], af, bf[ni]);
                }
            }
        }

        // ---- scatter acc -> q/k/v fp16 buffers (q pre-scaled, V transposed) ----
        #pragma unroll
        for (int mi = 0; mi < 4; mi++)
            #pragma unroll
            for (int ni = 0; ni < 3; ni++) {
                int nlog = (3 * warp + ni) * 8 + 2 * lm;
                #pragma unroll
                for (int r = 0; r < 4; r++) {
                    int row = mi * 16 + l4 + ((r & 2) ? 8 : 0);
                    int col = nlog + (r & 1);
                    int sec = col >> 6;
                    int wth = col & 63;
                    int head = wth >> 5, dd = wth & 31;
                    float v = acc[mi][ni][r];
                    if (sec == 0) v *= SCALE_ATT;
                    __half hv = __float2half_rn(v);
                    if (sec == 0)      qs [(head * 64 + row) * QH + dd] = hv;
                    else if (sec == 1) ksb[(head * 64 + row) * QH + dd] = hv;
                    else               vsb[(head * 32 + dd) * VH + row] = hv;
                }
            }
        __syncthreads();

        // ---- tensor-core attention (fp16 mma, fp32 softmax) ----
        {
            const int hip = warp >> 2;
            const int wg  = warp & 3;
            const __half* qb = qs  + hip * 64 * QH;
            const __half* kb = ksb + hip * 64 * QH;
            const __half* vb = vsb + hip * 32 * VH;
            __half* pwp = qs + warp * 16 * PH;

            // S = (Q*scale) . K^T  [16 x 64], K=32 -> 2 k16 steps
            float s[8][4];
            #pragma unroll
            for (int nt = 0; nt < 8; nt++)
                #pragma unroll
                for (int r = 0; r < 4; r++) s[nt][r] = 0.0f;

            #pragma unroll
            for (int ks = 0; ks < 2; ks++) {
                const int kk = ks * 16 + 2 * lm;
                const __half* ap = qb + (wg * 16 + l4) * QH + kk;
                uint32_t af[4];
                af[0] = *(const uint32_t*)ap;
                af[1] = *(const uint32_t*)(ap + 8 * QH);
                af[2] = *(const uint32_t*)(ap + 8);
                af[3] = *(const uint32_t*)(ap + 8 * QH + 8);
                #pragma unroll
                for (int nt = 0; nt < 8; nt++) {
                    const __half* bp = kb + (nt * 8 + l4) * QH + kk;
                    uint32_t bf[2];
                    bf[0] = *(const uint32_t*)bp;
                    bf[1] = *(const uint32_t*)(bp + 8);
                    mma_f16(s[nt], af, bf);
                }
            }

            // row softmax: rows l4, l4+8; row lives in a quad -> shfl 1,2
            float mx0 = s[0][0], mx1 = s[0][2];
            #pragma unroll
            for (int nt = 0; nt < 8; nt++) {
                mx0 = fmaxf(mx0, fmaxf(s[nt][0], s[nt][1]));
                mx1 = fmaxf(mx1, fmaxf(s[nt][2], s[nt][3]));
            }
            mx0 = fmaxf(mx0, __shfl_xor_sync(0xffffffffu, mx0, 1));
            mx0 = fmaxf(mx0, __shfl_xor_sync(0xffffffffu, mx0, 2));
            mx1 = fmaxf(mx1, __shfl_xor_sync(0xffffffffu, mx1, 1));
            mx1 = fmaxf(mx1, __shfl_xor_sync(0xffffffffu, mx1, 2));

            float sum0 = 0.0f, sum1 = 0.0f;
            #pragma unroll
            for (int nt = 0; nt < 8; nt++) {
                s[nt][0] = __expf(s[nt][0] - mx0); sum0 += s[nt][0];
                s[nt][1] = __expf(s[nt][1] - mx0); sum0 += s[nt][1];
                s[nt][2] = __expf(s[nt][2] - mx1); sum1 += s[nt][2];
                s[nt][3] = __expf(s[nt][3] - mx1); sum1 += s[nt][3];
            }
            sum0 += __shfl_xor_sync(0xffffffffu, sum0, 1);
            sum0 += __shfl_xor_sync(0xffffffffu, sum0, 2);
            sum1 += __shfl_xor_sync(0xffffffffu, sum1, 1);
            sum1 += __shfl_xor_sync(0xffffffffu, sum1, 2);
            const float inv0 = 1.0f / sum0;
            const float inv1 = 1.0f / sum1;

            // all warps must finish reading qs/ks before P overlays them
            __syncthreads();

            #pragma unroll
            for (int nt = 0; nt < 8; nt++) {
                *(__half2*)(pwp + l4 * PH + nt * 8 + 2 * lm) =
                    __floats2half2_rn(s[nt][0], s[nt][1]);
                *(__half2*)(pwp + (l4 + 8) * PH + nt * 8 + 2 * lm) =
                    __floats2half2_rn(s[nt][2], s[nt][3]);
            }
            __syncwarp();

            // O = P . V^T  [16 x 32], K=64 -> 4 k16 steps (normalize at store)
            float o[4][4];
            #pragma unroll
            for (int nt = 0; nt < 4; nt++)
                #pragma unroll
                for (int r = 0; r < 4; r++) o[nt][r] = 0.0f;

            #pragma unroll
            for (int ks = 0; ks < 4; ks++) {
                const int kk = ks * 16 + 2 * lm;
                const __half* ap = pwp + l4 * PH + kk;
                uint32_t af[4];
                af[0] = *(const uint32_t*)ap;
                af[1] = *(const uint32_t*)(ap + 8 * PH);
                af[2] = *(const uint32_t*)(ap + 8);
                af[3] = *(const uint32_t*)(ap + 8 * PH + 8);
                #pragma unroll
                for (int nt = 0; nt < 4; nt++) {
                    const __half* bp = vb + (nt * 8 + l4) * VH + kk;
                    uint32_t bf[2];
                    bf[0] = *(const uint32_t*)bp;
                    bf[1] = *(const uint32_t*)(bp + 8);
                    mma_f16(o[nt], af, bf);
                }
            }

            float* dst = g_O + ((size_t)win * 64 + wg * 16 + l4) * 384
                       + (hp * 2 + hip) * 32;
            #pragma unroll
            for (int nt = 0; nt < 4; nt++) {
                *(float2*)(dst + nt * 8 + 2 * lm) =
                    make_float2(o[nt][0] * inv0, o[nt][1] * inv0);
                *(float2*)(dst + 8 * 384 + nt * 8 + 2 * lm) =
                    make_float2(o[nt][2] * inv1, o[nt][3] * inv1);
            }
        }
    }
}

// ---------------------------------------------------------------------------
// K2: out = O @ w_out + b_out (fp16 mma), un-windowing scatter.
// CTA 128x128, K tiled by 32. Grid (3, 1024), nb fastest for L2 reuse of g_O.
// ---------------------------------------------------------------------------
__global__ void __launch_bounds__(256, 2) out_proj_kernel(
    const float* __restrict__ bout, float* __restrict__ out)
{
    __shared__ __half osA[128 * 40];
    __shared__ __half wsB[128 * 40];

    const int tid  = threadIdx.x;
    const int warp = tid >> 5, lane = tid & 31;
    const int l4 = lane >> 2, lm = lane & 3;
    const int mg = warp & 1, ng = warp >> 1;

    const int nb = blockIdx.x;                 // 0..2
    const int mb = blockIdx.y;                 // 0..1023
    const size_t row0 = (size_t)mb * 128;

    float acc[4][4][4];
    #pragma unroll
    for (int mi = 0; mi < 4; mi++)
        #pragma unroll
        for (int ni = 0; ni < 4; ni++)
            #pragma unroll
            for (int r = 0; r < 4; r++) acc[mi][ni][r] = 0.0f;

    float4 pa[4];
    uint4  pb[2];
    #pragma unroll
    for (int q = 0; q < 4; q++) {              // A: 128x32 fp32 -> 4 float4/thr
        int f = q * 256 + tid;
        int rA = f >> 3, cA = (f & 7) * 4;
        pa[q] = *(const float4*)(g_O + (row0 + rA) * 384 + cA);
    }
    #pragma unroll
    for (int q = 0; q < 2; q++) {              // B: 128x32 fp16 -> 2 uint4/thr
        int u = q * 256 + tid;
        int rB = u >> 2, seg = u & 3;
        pb[q] = *(const uint4*)(g_Woh + (size_t)(nb * 128 + rB) * 392 + seg * 8);
    }

    for (int kt = 0; kt < 12; kt++) {
        __syncthreads();
        #pragma unroll
        for (int q = 0; q < 4; q++) {
            int f = q * 256 + tid;
            int rA = f >> 3, cA = (f & 7) * 4;
            __half2* d = (__half2*)(osA + rA * 40 + cA);
            d[0] = __floats2half2_rn(pa[q].x, pa[q].y);
            d[1] = __floats2half2_rn(pa[q].z, pa[q].w);
        }
        #pragma unroll
        for (int q = 0; q < 2; q++) {
            int u = q * 256 + tid;
            int rB = u >> 2, seg = u & 3;
            *(uint4*)(wsB + rB * 40 + seg * 8) = pb[q];
        }
        __syncthreads();
        if (kt < 11) {
            #pragma unroll
            for (int q = 0; q < 4; q++) {
                int f = q * 256 + tid;
                int rA = f >> 3, cA = (f & 7) * 4;
                pa[q] = *(const float4*)(g_O + (row0 + rA) * 384 + (kt + 1) * 32 + cA);
            }
            #pragma unroll
            for (int q = 0; q < 2; q++) {
                int u = q * 256 + tid;
                int rB = u >> 2, seg = u & 3;
                pb[q] = *(const uint4*)(g_Woh + (size_t)(nb * 128 + rB) * 392
                                        + (kt + 1) * 32 + seg * 8);
            }
        }
        #pragma unroll
        for (int ks = 0; ks < 2; ks++) {
            const int kk = ks * 16 + 2 * lm;
            uint32_t bf[4][2];
            #pragma unroll
            for (int ni = 0; ni < 4; ni++) {
                const __half* p = wsB + (ng * 32 + ni * 8 + l4) * 40 + kk;
                bf[ni][0] = *(const uint32_t*)p;
                bf[ni][1] = *(const uint32_t*)(p + 8);
            }
            #pragma unroll
            for (int mi = 0; mi < 4; mi++) {
                const __half* p = osA + (mg * 64 + mi * 16 + l4) * 40 + kk;
                uint32_t af[4];
                af[0] = *(const uint32_t*)p;
                af[1] = *(const uint32_t*)(p + 8 * 40);
                af[2] = *(const uint32_t*)(p + 8);
                af[3] = *(const uint32_t*)(p + 8 * 40 + 8);
                #pragma unroll
                for (int ni = 0; ni < 4; ni++) mma_f16(acc[mi][ni], af, bf[ni]);
            }
        }
    }

    #pragma unroll
    for (int ni = 0; ni < 4; ni++) {
        int col = nb * 128 + ng * 32 + ni * 8 + 2 * lm;
        float bv0 = __ldg(bout + col), bv1 = __ldg(bout + col + 1);
        #pragma unroll
        for (int mi = 0; mi < 4; mi++) {
            #pragma unroll
            for (int half = 0; half < 2; half++) {
                int grow = (int)row0 + mg * 64 + mi * 16 + l4 + half * 8;
                int wwin = grow >> 6, t = grow & 63;
                int bbb = wwin >> 6, rr = wwin & 63;
                int nhi = rr >> 3, nwi = rr & 7;
                int i = t >> 3, j = t & 7;
                size_t g = (((size_t)(bbb * 64 + nhi * 8 + i)) * 64 + nwi * 8 + j) * 384 + col;
                float2 v;
                v.x = acc[mi][ni][half * 2 + 0] + bv0;
                v.y = acc[mi][ni][half * 2 + 1] + bv1;
                *(float2*)(out + g) = v;
            }
        }
    }
}

extern "C" void kernel_launch(void* const* d_in, const int* in_sizes, int n_in,
                              void* d_out, int out_size) {
    (void)in_sizes; (void)n_in; (void)out_size;
    const float* x    = (const float*)d_in[0];
    const float* wqkv = (const float*)d_in[1];
    const float* wout = (const float*)d_in[2];
    const float* bout = (const float*)d_in[3];
    float* out = (float*)d_out;

    prep_weights<<<2304, 256>>>(wqkv, wout);

    cudaFuncSetAttribute(qkv_attn_kernel,
                         cudaFuncAttributeMaxDynamicSharedMemorySize, SMEM_K1_BYTES);
    qkv_attn_kernel<<<2048, 256, SMEM_K1_BYTES>>>(x);
    out_proj_kernel<<<dim3(3, 1024), 256>>>(bout, out);
}

// round 13
// speedup vs baseline: 2.6781x; 1.0853x over previous
#include <cuda_runtime.h>
#include <cuda_fp16.h>
#include <cstdint>

// Shapes
//   x:      [32, 64, 64, 384] fp32
//   w_qkv:  [384, 1152] fp32
//   w_out:  [384, 384]  fp32
//   b_out:  [384]       fp32
//   out:    [32, 64, 64, 384] fp32
// 2048 windows, 64 tokens each, 12 heads x 32.

#define SCALE_ATT 0.17677669529663687f   // 32^-0.5

// Scratch (static device mem, allowed)
__device__ __half g_Oh[50331648];       // attention out [2048*64][384] fp16
__device__ __half g_Wqh[1152 * 392];    // w_qkv^T  [n=1152][k=384 +8 pad] fp16
__device__ __half g_Woh[384 * 392];     // w_out^T  [n=384][k=384 +8 pad] fp16

__device__ __forceinline__ void mma_f16(float (&d)[4], const uint32_t (&a)[4],
                                        uint32_t b0, uint32_t b1) {
    asm volatile(
        "mma.sync.aligned.m16n8k16.row.col.f32.f16.f16.f32 "
        "{%0,%1,%2,%3}, {%4,%5,%6,%7}, {%8,%9}, {%0,%1,%2,%3};\n"
        : "+f"(d[0]), "+f"(d[1]), "+f"(d[2]), "+f"(d[3])
        : "r"(a[0]), "r"(a[1]), "r"(a[2]), "r"(a[3]), "r"(b0), "r"(b1));
}

__device__ __forceinline__ uint32_t cvs(const void* p) {
    return (uint32_t)__cvta_generic_to_shared(p);
}
__device__ __forceinline__ void ldsm4(uint32_t (&r)[4], uint32_t a) {
    asm volatile("ldmatrix.sync.aligned.m8n8.x4.shared.b16 {%0,%1,%2,%3}, [%4];"
                 : "=r"(r[0]), "=r"(r[1]), "=r"(r[2]), "=r"(r[3]) : "r"(a));
}
__device__ __forceinline__ void ldsm2(uint32_t (&r)[2], uint32_t a) {
    asm volatile("ldmatrix.sync.aligned.m8n8.x2.shared.b16 {%0,%1}, [%2];"
                 : "=r"(r[0]), "=r"(r[1]) : "r"(a));
}

// ---------------------------------------------------------------------------
// K0: transpose + fp16-convert weights.
// ---------------------------------------------------------------------------
__global__ void prep_weights(const float* __restrict__ wqkv,
                             const float* __restrict__ wout)
{
    int i = blockIdx.x * 256 + threadIdx.x;
    if (i < 384 * 1152) {
        int k = i / 1152, n = i % 1152;
        g_Wqh[n * 392 + k] = __float2half_rn(wqkv[i]);
    } else {
        int j = i - 384 * 1152;
        if (j < 384 * 384) {
            int k = j / 384, n = j % 384;
            g_Woh[n * 392 + k] = __float2half_rn(wout[j]);
        }
    }
}

// ---------------------------------------------------------------------------
// K1: fused QKV GEMM + windowed attention, fp16 mma + ldmatrix. occ 2.
// smem halves: xs[64][392] @0 ; ws0[192][40] @25088 ; ws1 @32768 ;
//              qs[2][64][40] @40448 ; ks @45568 ; vs[2][32][72] @50688
// total 55296 halves = 110592 B. P overlays qs/ks (8*16*72 = 9216 <= 10240).
// ---------------------------------------------------------------------------
#define XH 392
#define WH 40
#define QH 40
#define VH 72
#define PH 72
#define SMEM_K1_BYTES (55296 * 2)

__global__ void __launch_bounds__(256, 2) qkv_attn_kernel(
    const float* __restrict__ x)
{
    extern __shared__ __half smh[];
    __half* xs  = smh;
    __half* ws0 = smh + 25088;
    __half* ws1 = smh + 32768;
    __half* qs  = smh + 40448;
    __half* ksb = smh + 45568;
    __half* vsb = smh + 50688;

    const int tid  = threadIdx.x;
    const int warp = tid >> 5, lane = tid & 31;
    const int l4 = lane >> 2, lm = lane & 3;

    // ldmatrix per-lane offsets (in halves):
    //  A-type (row-major [m][k]): matrices (m0-7,k0-7),(m8-15,k0-7),(m0-7,k8-15),(m8-15,k8-15)
    const int arow = lane & 15;
    const int acol = (lane >> 4) << 3;
    //  B-type ([n][k], x4 over two n8 tiles): (n0-7,k0-7),(n0-7,k8-15),(n8-15,k0-7),(n8-15,k8-15)
    const int brow = ((lane >> 4) << 3) + (lane & 7);
    const int bcol = ((lane >> 3) & 1) << 3;

    const uint32_t xs_s  = cvs(xs);
    const uint32_t ws0_s = cvs(ws0), ws1_s = cvs(ws1);
    const uint32_t qs_s  = cvs(qs),  ks_s  = cvs(ksb), vs_s = cvs(vsb);

    const int win = blockIdx.x;
    const int bb  = win >> 6, rem = win & 63, nhi = rem >> 3, nwi = rem & 7;

    // ---- load x window -> fp16 smem, coalesced ----
    {
        const size_t base = ((size_t)(bb * 64 + nhi * 8) * 64 + nwi * 8) * 384;
        #pragma unroll
        for (int q = 0; q < 24; q++) {
            int f   = q * 256 + tid;
            int row = f / 96;
            int c4  = (f - row * 96) * 4;
            int i = row >> 3, j = row & 7;
            float4 v = *(const float4*)(x + base + ((size_t)i * 64 + j) * 384 + c4);
            __half2* d = (__half2*)(xs + row * XH + c4);
            d[0] = __floats2half2_rn(v.x, v.y);
            d[1] = __floats2half2_rn(v.z, v.w);
        }
    }
    __syncthreads();

    // ---- head pairs: QKV GEMM (64 x 192, K=384) then attention ----
    for (int hp = 0; hp < 6; hp++) {
        float acc[4][3][4];
        #pragma unroll
        for (int mi = 0; mi < 4; mi++)
            #pragma unroll
            for (int ni = 0; ni < 3; ni++)
                #pragma unroll
                for (int r = 0; r < 4; r++) acc[mi][ni][r] = 0.0f;

        // weight tile: 192 n-rows x 32 k-halves per kt; 3 uint4/thread
        const __half* gwp[3];
        int so[3];
        #pragma unroll
        for (int q = 0; q < 3; q++) {
            int u = q * 256 + tid;
            int rown = u >> 2, seg = u & 3;
            int sec = rown >> 6, nin = rown & 63;
            gwp[q] = g_Wqh + (size_t)(sec * 384 + hp * 64 + nin) * 392 + seg * 8;
            so[q]  = rown * WH + seg * 8;
        }
        uint4 pf[3];
        #pragma unroll
        for (int q = 0; q < 3; q++) pf[q] = *(const uint4*)(gwp[q]);

        for (int kt = 0; kt < 12; kt++) {
            __half* wsp = (kt & 1) ? ws1 : ws0;
            const uint32_t wb = (kt & 1) ? ws1_s : ws0_s;
            #pragma unroll
            for (int q = 0; q < 3; q++) *(uint4*)(wsp + so[q]) = pf[q];
            __syncthreads();
            if (kt < 11) {
                #pragma unroll
                for (int q = 0; q < 3; q++)
                    pf[q] = *(const uint4*)(gwp[q] + (kt + 1) * 32);
            }
            #pragma unroll
            for (int ks = 0; ks < 2; ks++) {
                const int kk = ks * 16;
                uint32_t bA[4], bC[2];
                ldsm4(bA, wb + 2 * ((warp * 24 + brow) * WH + kk + bcol));
                ldsm2(bC, wb + 2 * ((warp * 24 + 16 + (lane & 7)) * WH + kk
                                    + (((lane >> 3) & 1) << 3)));
                #pragma unroll
                for (int mi = 0; mi < 4; mi++) {
                    uint32_t af[4];
                    ldsm4(af, xs_s + 2 * ((mi * 16 + arow) * XH + kt * 32 + kk + acol));
                    mma_f16(acc[mi][0], af, bA[0], bA[1]);
                    mma_f16(acc[mi][1], af, bA[2], bA[3]);
                    mma_f16(acc[mi][2], af, bC[0], bC[1]);
                }
            }
        }

        // ---- scatter acc -> q/k/v fp16 buffers (q pre-scaled, V transposed) ----
        #pragma unroll
        for (int mi = 0; mi < 4; mi++)
            #pragma unroll
            for (int ni = 0; ni < 3; ni++) {
                int nlog = (3 * warp + ni) * 8 + 2 * lm;
                #pragma unroll
                for (int r = 0; r < 4; r++) {
                    int row = mi * 16 + l4 + ((r & 2) ? 8 : 0);
                    int col = nlog + (r & 1);
                    int sec = col >> 6;
                    int wth = col & 63;
                    int head = wth >> 5, dd = wth & 31;
                    float v = acc[mi][ni][r];
                    if (sec == 0) v *= SCALE_ATT;
                    __half hv = __float2half_rn(v);
                    if (sec == 0)      qs [(head * 64 + row) * QH + dd] = hv;
                    else if (sec == 1) ksb[(head * 64 + row) * QH + dd] = hv;
                    else               vsb[(head * 32 + dd) * VH + row] = hv;
                }
            }
        __syncthreads();

        // ---- tensor-core attention (fp16 mma + ldmatrix, fp32 softmax) ----
        {
            const int hip = warp >> 2;
            const int wg  = warp & 3;
            const uint32_t qb = qs_s + 2 * (hip * 64 * QH);
            const uint32_t kb = ks_s + 2 * (hip * 64 * QH);
            const uint32_t vb = vs_s + 2 * (hip * 32 * VH);
            __half* pwp = qs + warp * 16 * PH;
            const uint32_t pb = cvs(pwp);

            // S = (Q*scale) . K^T  [16 x 64], K=32 -> 2 k16 steps
            float s[8][4];
            #pragma unroll
            for (int nt = 0; nt < 8; nt++)
                #pragma unroll
                for (int r = 0; r < 4; r++) s[nt][r] = 0.0f;

            #pragma unroll
            for (int ks = 0; ks < 2; ks++) {
                const int kk = ks * 16;
                uint32_t af[4];
                ldsm4(af, qb + 2 * ((wg * 16 + arow) * QH + kk + acol));
                #pragma unroll
                for (int t = 0; t < 4; t++) {
                    uint32_t bf[4];
                    ldsm4(bf, kb + 2 * ((t * 16 + brow) * QH + kk + bcol));
                    mma_f16(s[2 * t + 0], af, bf[0], bf[1]);
                    mma_f16(s[2 * t + 1], af, bf[2], bf[3]);
                }
            }

            // row softmax: rows l4, l4+8; row lives in a quad -> shfl 1,2
            float mx0 = s[0][0], mx1 = s[0][2];
            #pragma unroll
            for (int nt = 0; nt < 8; nt++) {
                mx0 = fmaxf(mx0, fmaxf(s[nt][0], s[nt][1]));
                mx1 = fmaxf(mx1, fmaxf(s[nt][2], s[nt][3]));
            }
            mx0 = fmaxf(mx0, __shfl_xor_sync(0xffffffffu, mx0, 1));
            mx0 = fmaxf(mx0, __shfl_xor_sync(0xffffffffu, mx0, 2));
            mx1 = fmaxf(mx1, __shfl_xor_sync(0xffffffffu, mx1, 1));
            mx1 = fmaxf(mx1, __shfl_xor_sync(0xffffffffu, mx1, 2));

            float sum0 = 0.0f, sum1 = 0.0f;
            #pragma unroll
            for (int nt = 0; nt < 8; nt++) {
                s[nt][0] = __expf(s[nt][0] - mx0); sum0 += s[nt][0];
                s[nt][1] = __expf(s[nt][1] - mx0); sum0 += s[nt][1];
                s[nt][2] = __expf(s[nt][2] - mx1); sum1 += s[nt][2];
                s[nt][3] = __expf(s[nt][3] - mx1); sum1 += s[nt][3];
            }
            sum0 += __shfl_xor_sync(0xffffffffu, sum0, 1);
            sum0 += __shfl_xor_sync(0xffffffffu, sum0, 2);
            sum1 += __shfl_xor_sync(0xffffffffu, sum1, 1);
            sum1 += __shfl_xor_sync(0xffffffffu, sum1, 2);
            const float inv0 = 1.0f / sum0;
            const float inv1 = 1.0f / sum1;

            // all warps must finish reading qs/ks before P overlays them
            __syncthreads();

            #pragma unroll
            for (int nt = 0; nt < 8; nt++) {
                *(__half2*)(pwp + l4 * PH + nt * 8 + 2 * lm) =
                    __floats2half2_rn(s[nt][0], s[nt][1]);
                *(__half2*)(pwp + (l4 + 8) * PH + nt * 8 + 2 * lm) =
                    __floats2half2_rn(s[nt][2], s[nt][3]);
            }
            __syncwarp();

            // O = P . V^T  [16 x 32], K=64 -> 4 k16 steps (normalize at store)
            float o[4][4];
            #pragma unroll
            for (int nt = 0; nt < 4; nt++)
                #pragma unroll
                for (int r = 0; r < 4; r++) o[nt][r] = 0.0f;

            #pragma unroll
            for (int ks = 0; ks < 4; ks++) {
                const int kk = ks * 16;
                uint32_t af[4];
                ldsm4(af, pb + 2 * (arow * PH + kk + acol));
                #pragma unroll
                for (int t = 0; t < 2; t++) {
                    uint32_t bf[4];
                    ldsm4(bf, vb + 2 * ((t * 16 + brow) * VH + kk + bcol));
                    mma_f16(o[2 * t + 0], af, bf[0], bf[1]);
                    mma_f16(o[2 * t + 1], af, bf[2], bf[3]);
                }
            }

            __half* dst = g_Oh + ((size_t)win * 64 + wg * 16 + l4) * 384
                        + (hp * 2 + hip) * 32;
            #pragma unroll
            for (int nt = 0; nt < 4; nt++) {
                *(__half2*)(dst + nt * 8 + 2 * lm) =
                    __floats2half2_rn(o[nt][0] * inv0, o[nt][1] * inv0);
                *(__half2*)(dst + 8 * 384 + nt * 8 + 2 * lm) =
                    __floats2half2_rn(o[nt][2] * inv1, o[nt][3] * inv1);
            }
        }
    }
}

// ---------------------------------------------------------------------------
// K2: out = O @ w_out + b_out (fp16 mma + ldmatrix), un-windowing scatter.
// CTA 128x128, K tiled by 32. Grid (3, 1024), nb fastest for L2 reuse of g_Oh.
// ---------------------------------------------------------------------------
__global__ void __launch_bounds__(256, 2) out_proj_kernel(
    const float* __restrict__ bout, float* __restrict__ out)
{
    __shared__ __half osA[128 * 40];
    __shared__ __half wsB[128 * 40];

    const int tid  = threadIdx.x;
    const int warp = tid >> 5, lane = tid & 31;
    const int l4 = lane >> 2, lm = lane & 3;
    const int mg = warp & 1, ng = warp >> 1;

    const int arow = lane & 15;
    const int acol = (lane >> 4) << 3;
    const int brow = ((lane >> 4) << 3) + (lane & 7);
    const int bcol = ((lane >> 3) & 1) << 3;
    const uint32_t oa_s = cvs(osA), wb_s = cvs(wsB);

    const int nb = blockIdx.x;                 // 0..2
    const int mb = blockIdx.y;                 // 0..1023
    const size_t row0 = (size_t)mb * 128;

    float acc[4][4][4];
    #pragma unroll
    for (int mi = 0; mi < 4; mi++)
        #pragma unroll
        for (int ni = 0; ni < 4; ni++)
            #pragma unroll
            for (int r = 0; r < 4; r++) acc[mi][ni][r] = 0.0f;

    uint4 pa[2], pb[2];
    #pragma unroll
    for (int q = 0; q < 2; q++) {              // A: 128x32 fp16 -> 2 uint4/thr
        int u = q * 256 + tid;
        int rA = u >> 2, seg = u & 3;
        pa[q] = *(const uint4*)(g_Oh + (row0 + rA) * 384 + seg * 8);
        pb[q] = *(const uint4*)(g_Woh + (size_t)(nb * 128 + rA) * 392 + seg * 8);
    }

    for (int kt = 0; kt < 12; kt++) {
        __syncthreads();
        #pragma unroll
        for (int q = 0; q < 2; q++) {
            int u = q * 256 + tid;
            int rA = u >> 2, seg = u & 3;
            *(uint4*)(osA + rA * 40 + seg * 8) = pa[q];
            *(uint4*)(wsB + rA * 40 + seg * 8) = pb[q];
        }
        __syncthreads();
        if (kt < 11) {
            #pragma unroll
            for (int q = 0; q < 2; q++) {
                int u = q * 256 + tid;
                int rA = u >> 2, seg = u & 3;
                pa[q] = *(const uint4*)(g_Oh + (row0 + rA) * 384
                                        + (kt + 1) * 32 + seg * 8);
                pb[q] = *(const uint4*)(g_Woh + (size_t)(nb * 128 + rA) * 392
                                        + (kt + 1) * 32 + seg * 8);
            }
        }
        #pragma unroll
        for (int ks = 0; ks < 2; ks++) {
            const int kk = ks * 16;
            uint32_t bf[2][4];
            #pragma unroll
            for (int t = 0; t < 2; t++)
                ldsm4(bf[t], wb_s + 2 * ((ng * 32 + t * 16 + brow) * 40 + kk + bcol));
            #pragma unroll
            for (int mi = 0; mi < 4; mi++) {
                uint32_t af[4];
                ldsm4(af, oa_s + 2 * ((mg * 64 + mi * 16 + arow) * 40 + kk + acol));
                mma_f16(acc[mi][0], af, bf[0][0], bf[0][1]);
                mma_f16(acc[mi][1], af, bf[0][2], bf[0][3]);
                mma_f16(acc[mi][2], af, bf[1][0], bf[1][1]);
                mma_f16(acc[mi][3], af, bf[1][2], bf[1][3]);
            }
        }
    }

    #pragma unroll
    for (int ni = 0; ni < 4; ni++) {
        int col = nb * 128 + ng * 32 + ni * 8 + 2 * lm;
        float bv0 = __ldg(bout + col), bv1 = __ldg(bout + col + 1);
        #pragma unroll
        for (int mi = 0; mi < 4; mi++) {
            #pragma unroll
            for (int half = 0; half < 2; half++) {
                int grow = (int)row0 + mg * 64 + mi * 16 + l4 + half * 8;
                int wwin = grow >> 6, t = grow & 63;
                int bbb = wwin >> 6, rr = wwin & 63;
                int nhi = rr >> 3, nwi = rr & 7;
                int i = t >> 3, j = t & 7;
                size_t g = (((size_t)(bbb * 64 + nhi * 8 + i)) * 64 + nwi * 8 + j) * 384 + col;
                float2 v;
                v.x = acc[mi][ni][half * 2 + 0] + bv0;
                v.y = acc[mi][ni][half * 2 + 1] + bv1;
                *(float2*)(out + g) = v;
            }
        }
    }
}

extern "C" void kernel_launch(void* const* d_in, const int* in_sizes, int n_in,
                              void* d_out, int out_size) {
    (void)in_sizes; (void)n_in; (void)out_size;
    const float* x    = (const float*)d_in[0];
    const float* wqkv = (const float*)d_in[1];
    const float* wout = (const float*)d_in[2];
    const float* bout = (const float*)d_in[3];
    float* out = (float*)d_out;

    prep_weights<<<2304, 256>>>(wqkv, wout);

    cudaFuncSetAttribute(qkv_attn_kernel,
                         cudaFuncAttributeMaxDynamicSharedMemorySize, SMEM_K1_BYTES);
    qkv_attn_kernel<<<2048, 256, SMEM_K1_BYTES>>>(x);
    out_proj_kernel<<<dim3(3, 1024), 256>>>(bout, out);
}